// round 1
// baseline (speedup 1.0000x reference)
#include <cuda_runtime.h>
#include <math.h>

#define B_   2
#define S_   4096
#define DM   512
#define H_   8
#define DH   64
#define HB   (H_*B_)                       // 16
#define NROWS (B_*S_)                      // 8192
#define CTX_ELEMS ((size_t)B_*S_*DM)       // 4,194,304

// Scratch: projected q/k/v in [h][b][s][d] layout, 16 MB each.
__device__ float g_q[(size_t)HB*S_*DH];
__device__ float g_k[(size_t)HB*S_*DH];
__device__ float g_v[(size_t)HB*S_*DH];

// ---------------------------------------------------------------------------
// Projection: Y = X @ W + bias, scattered into [h][b][s][d] layout.
// Grid: (DM/64, NROWS/64, 3), 256 threads. z selects q/k/v.
// ---------------------------------------------------------------------------
__global__ __launch_bounds__(256)
void proj_kernel(const float* __restrict__ Xq, const float* __restrict__ Xk,
                 const float* __restrict__ Xv,
                 const float* __restrict__ Wq, const float* __restrict__ Wk,
                 const float* __restrict__ Wv,
                 const float* __restrict__ bq, const float* __restrict__ bk,
                 const float* __restrict__ bv)
{
    const float* X; const float* W; const float* bias; float* out;
    if (blockIdx.z == 0)      { X = Xq; W = Wq; bias = bq; out = g_q; }
    else if (blockIdx.z == 1) { X = Xk; W = Wk; bias = bk; out = g_k; }
    else                      { X = Xv; W = Wv; bias = bv; out = g_v; }

    __shared__ float Xs[64][65];   // [k][m] transposed, padded
    __shared__ float Ws[64][64];   // [k][c]

    const int n0 = blockIdx.y * 64;
    const int c0 = blockIdx.x * 64;
    const int tid = threadIdx.x;
    const int tx = tid & 15, ty = tid >> 4;

    float acc[4][4] = {};

    for (int k0 = 0; k0 < DM; k0 += 64) {
        #pragma unroll
        for (int l = tid; l < 64*64; l += 256) {
            int m = l >> 6, kk = l & 63;
            Xs[kk][m] = X[(size_t)(n0 + m) * DM + (k0 + kk)];
        }
        #pragma unroll
        for (int l = tid; l < 64*64; l += 256) {
            int kk = l >> 6, c = l & 63;
            Ws[kk][c] = W[(size_t)(k0 + kk) * DM + (c0 + c)];
        }
        __syncthreads();
        #pragma unroll 16
        for (int kk = 0; kk < 64; kk++) {
            float a[4], bb[4];
            #pragma unroll
            for (int r = 0; r < 4; r++) a[r]  = Xs[kk][ty*4 + r];
            #pragma unroll
            for (int s = 0; s < 4; s++) bb[s] = Ws[kk][tx*4 + s];
            #pragma unroll
            for (int r = 0; r < 4; r++)
                #pragma unroll
                for (int s = 0; s < 4; s++)
                    acc[r][s] = fmaf(a[r], bb[s], acc[r][s]);
        }
        __syncthreads();
    }

    const int h = c0 >> 6;   // tile spans exactly one head
    #pragma unroll
    for (int r = 0; r < 4; r++) {
        int n = n0 + ty*4 + r;
        int b = n / S_, srow = n - b * S_;
        size_t base = (((size_t)(h * B_ + b) * S_) + srow) * DH;
        #pragma unroll
        for (int s = 0; s < 4; s++) {
            int c = c0 + tx*4 + s;
            out[base + (c & 63)] = acc[r][s] + bias[c];
        }
    }
}

// ---------------------------------------------------------------------------
// Scores: attn_raw[hb][i][j] = 0.125 * sum_d q[hb,i,d] * k[hb,j,d]
// Grid: (S/64, S/64, HB), 256 threads. Writes raw scores into attn region.
// ---------------------------------------------------------------------------
__global__ __launch_bounds__(256)
void scores_kernel(float* __restrict__ attn)
{
    const int hb = blockIdx.z;
    const int i0 = blockIdx.y * 64;
    const int j0 = blockIdx.x * 64;
    const float* Q = g_q + (size_t)hb * S_ * DH;
    const float* K = g_k + (size_t)hb * S_ * DH;

    __shared__ float Qs[64][65];   // [d][m]
    __shared__ float Ks[64][65];   // [d][n]

    const int tid = threadIdx.x;
    const int tx = tid & 15, ty = tid >> 4;

    #pragma unroll
    for (int l = tid; l < 64*64; l += 256) {
        int m = l >> 6, d = l & 63;
        Qs[d][m] = Q[(size_t)(i0 + m) * DH + d];
        Ks[d][m] = K[(size_t)(j0 + m) * DH + d];
    }
    __syncthreads();

    float acc[4][4] = {};
    #pragma unroll 16
    for (int d = 0; d < 64; d++) {
        float a[4], bb[4];
        #pragma unroll
        for (int r = 0; r < 4; r++) a[r]  = Qs[d][ty*4 + r];
        #pragma unroll
        for (int s = 0; s < 4; s++) bb[s] = Ks[d][tx*4 + s];
        #pragma unroll
        for (int r = 0; r < 4; r++)
            #pragma unroll
            for (int s = 0; s < 4; s++)
                acc[r][s] = fmaf(a[r], bb[s], acc[r][s]);
    }

    const float scale = 0.125f;   // 1/sqrt(64)
    #pragma unroll
    for (int r = 0; r < 4; r++) {
        size_t idx = ((size_t)hb * S_ + (i0 + ty*4 + r)) * S_ + j0 + tx*4;
        float4 o = make_float4(acc[r][0]*scale, acc[r][1]*scale,
                               acc[r][2]*scale, acc[r][3]*scale);
        *reinterpret_cast<float4*>(&attn[idx]) = o;
    }
}

// ---------------------------------------------------------------------------
// Softmax over each row of 4096, in place. Grid: HB*S blocks, 256 threads.
// ---------------------------------------------------------------------------
__global__ __launch_bounds__(256)
void softmax_kernel(float* __restrict__ attn)
{
    float* p = attn + (size_t)blockIdx.x * S_;
    const int tid = threadIdx.x;

    float v[16];
    float m = -1e30f;
    #pragma unroll
    for (int i = 0; i < 16; i++) {
        v[i] = p[tid + i * 256];
        m = fmaxf(m, v[i]);
    }
    #pragma unroll
    for (int off = 16; off; off >>= 1)
        m = fmaxf(m, __shfl_xor_sync(0xffffffffu, m, off));

    __shared__ float redm[8];
    __shared__ float reds[8];
    if ((tid & 31) == 0) redm[tid >> 5] = m;
    __syncthreads();
    float bm = redm[0];
    #pragma unroll
    for (int i = 1; i < 8; i++) bm = fmaxf(bm, redm[i]);

    float sum = 0.f;
    #pragma unroll
    for (int i = 0; i < 16; i++) {
        v[i] = expf(v[i] - bm);
        sum += v[i];
    }
    #pragma unroll
    for (int off = 16; off; off >>= 1)
        sum += __shfl_xor_sync(0xffffffffu, sum, off);
    if ((tid & 31) == 0) reds[tid >> 5] = sum;
    __syncthreads();
    float bs = 0.f;
    #pragma unroll
    for (int i = 0; i < 8; i++) bs += reds[i];

    const float inv = 1.0f / bs;
    #pragma unroll
    for (int i = 0; i < 16; i++)
        p[tid + i * 256] = v[i] * inv;
}

// ---------------------------------------------------------------------------
// Context: ctx[b,s, h*64+d] = sum_j attn[hb,s,j] * v[hb,j,d]
// Grid: (S/64, HB), 256 threads.
// ---------------------------------------------------------------------------
__global__ __launch_bounds__(256)
void context_kernel(const float* __restrict__ attn, float* __restrict__ ctx)
{
    const int hb = blockIdx.y;
    const int i0 = blockIdx.x * 64;
    const int h = hb / B_, b = hb % B_;
    const float* P = attn + (size_t)hb * S_ * S_ + (size_t)i0 * S_;
    const float* V = g_v + (size_t)hb * S_ * DH;

    __shared__ float Ps[64][65];   // [k][m] transposed, padded
    __shared__ float Vs[64][64];   // [k][d]

    const int tid = threadIdx.x;
    const int tx = tid & 15, ty = tid >> 4;

    float acc[4][4] = {};

    for (int k0 = 0; k0 < S_; k0 += 64) {
        #pragma unroll
        for (int l = tid; l < 64*64; l += 256) {
            int m = l >> 6, kk = l & 63;
            Ps[kk][m] = P[(size_t)m * S_ + (k0 + kk)];
        }
        #pragma unroll
        for (int l = tid; l < 64*64; l += 256) {
            int kk = l >> 6, d = l & 63;
            Vs[kk][d] = V[(size_t)(k0 + kk) * DH + d];
        }
        __syncthreads();
        #pragma unroll 16
        for (int kk = 0; kk < 64; kk++) {
            float a[4], bb[4];
            #pragma unroll
            for (int r = 0; r < 4; r++) a[r]  = Ps[kk][ty*4 + r];
            #pragma unroll
            for (int s = 0; s < 4; s++) bb[s] = Vs[kk][tx*4 + s];
            #pragma unroll
            for (int r = 0; r < 4; r++)
                #pragma unroll
                for (int s = 0; s < 4; s++)
                    acc[r][s] = fmaf(a[r], bb[s], acc[r][s]);
        }
        __syncthreads();
    }

    #pragma unroll
    for (int r = 0; r < 4; r++) {
        int srow = i0 + ty*4 + r;
        size_t base = ((size_t)b * S_ + srow) * DM + h * 64 + tx*4;
        float4 o = make_float4(acc[r][0], acc[r][1], acc[r][2], acc[r][3]);
        *reinterpret_cast<float4*>(&ctx[base]) = o;
    }
}

// ---------------------------------------------------------------------------
extern "C" void kernel_launch(void* const* d_in, const int* in_sizes, int n_in,
                              void* d_out, int out_size)
{
    const float* query = (const float*)d_in[0];
    const float* key   = (const float*)d_in[1];
    const float* value = (const float*)d_in[2];
    const float* Wq    = (const float*)d_in[3];
    const float* bq    = (const float*)d_in[4];
    const float* Wk    = (const float*)d_in[5];
    const float* bk    = (const float*)d_in[6];
    const float* Wv    = (const float*)d_in[7];
    const float* bv    = (const float*)d_in[8];

    float* ctx  = (float*)d_out;              // [B, S, DM]
    float* attn = (float*)d_out + CTX_ELEMS;  // [HB, S, S]

    // 1) projections into g_q/g_k/g_v
    {
        dim3 grid(DM / 64, NROWS / 64, 3);
        proj_kernel<<<grid, 256>>>(query, key, value, Wq, Wk, Wv, bq, bk, bv);
    }
    // 2) raw scores into attn region
    {
        dim3 grid(S_ / 64, S_ / 64, HB);
        scores_kernel<<<grid, 256>>>(attn);
    }
    // 3) softmax in place
    {
        softmax_kernel<<<HB * S_, 256>>>(attn);
    }
    // 4) context = attn @ v
    {
        dim3 grid(S_ / 64, HB);
        context_kernel<<<grid, 256>>>(attn, ctx);
    }
}